// round 12
// baseline (speedup 1.0000x reference)
#include <cuda_runtime.h>

// CTRNN forward on GB300 — round 8: single kernel, augmented-operand scan.
// The input projection is folded into the recurrent dot: per step each lane
// computes [h(64); x_t(32)] . [aW_hh[j,:] | aW_in[j,:]] (k-packed f32x2).
// Structure = the proven round-8 scan: 2 warps/CTA, 1 output per lane, one
// __syncthreads per step, double-buffered h. Warp 0 stages raw x through an
// 8-deep register ring into a 16-deep smem ring (branch-free, clamped LDG).
// Inputs (metadata order): x[B,T,D] f32, seq_lengths[B] i32 (forward no-op),
// W_in[H,D] f32, b_in[H] f32, W_hh[H,H] f32, b_hh[H] f32.
// Output: outputs[B,T,H] then h_last[B,H], f32, concatenated flat.

#define BB 256
#define TT 2048
#define DD 32
#define HH 64

typedef unsigned long long u64;

__device__ __forceinline__ u64 pack2(float lo, float hi) {
    u64 r; asm("mov.b64 %0, {%1, %2};" : "=l"(r) : "f"(lo), "f"(hi)); return r;
}
__device__ __forceinline__ float2 unpack2(u64 v) {
    float2 f; asm("mov.b64 {%0, %1}, %2;" : "=f"(f.x), "=f"(f.y) : "l"(v)); return f;
}
// Packed fp32x2 FMA (Blackwell FFMA2): d = a*b + d.
__device__ __forceinline__ void ffma2(u64& d, u64 a, u64 b) {
    asm("fma.rn.f32x2 %0, %1, %2, %0;" : "+l"(d) : "l"(a), "l"(b));
}
__device__ __forceinline__ u64 add2(u64 a, u64 b) {
    u64 r; asm("add.rn.f32x2 %0, %1, %2;" : "=l"(r) : "l"(a), "l"(b)); return r;
}

#define ALPHA_F ((float)(16.67 / 40.0))
#define OMA_F   ((float)(1.0 - 16.67 / 40.0))

__global__ void __launch_bounds__(HH) ctrnn_aug_kernel(
    const float* __restrict__ x,
    const float* __restrict__ W_in,
    const float* __restrict__ b_in,
    const float* __restrict__ W_hh,
    const float* __restrict__ b_hh,
    float* __restrict__ out)
{
    const int b = blockIdx.x;
    const int j = threadIdx.x;      // output index 0..63
    const int l = j & 31;

    __shared__ __align__(16) float hbuf[2][HH];    // hidden state, dbl-buffered
    __shared__ __align__(16) float xbuf[16][DD];   // raw x ring, 16 steps deep

    // --- k-packed weights, pre-scaled by ALPHA: 48 u64 = 96 regs ---
    u64 wk[HH / 2];                  // ALPHA*W_hh[j,:]
    #pragma unroll
    for (int k4 = 0; k4 < HH / 4; k4++) {
        float4 v = ((const float4*)(W_hh + j * HH))[k4];
        wk[2 * k4]     = pack2(ALPHA_F * v.x, ALPHA_F * v.y);
        wk[2 * k4 + 1] = pack2(ALPHA_F * v.z, ALPHA_F * v.w);
    }
    u64 wi[DD / 2];                  // ALPHA*W_in[j,:]
    #pragma unroll
    for (int k4 = 0; k4 < DD / 4; k4++) {
        float4 v = ((const float4*)(W_in + j * DD))[k4];
        wi[2 * k4]     = pack2(ALPHA_F * v.x, ALPHA_F * v.y);
        wi[2 * k4 + 1] = pack2(ALPHA_F * v.z, ALPHA_F * v.w);
    }
    const u64 BIAS2 = pack2(ALPHA_F * (b_in[j] + b_hh[j]), 0.0f);
    const u64 OMA2  = pack2(OMA_F, 0.0f);

    const float* xg = x + (size_t)b * TT * DD;
    const bool stager = (j < DD);    // warp 0: stages one x element per step

    // --- prologue: xbuf[0..7] = x[0..7]; register ring xr[p] = x[8+p] ---
    float xr[8];
    if (stager) {
        #pragma unroll
        for (int s = 0; s < 8; s++) xbuf[s][l] = xg[s * DD + l];
        #pragma unroll
        for (int p = 0; p < 8; p++) xr[p] = xg[(8 + p) * DD + l];
    }
    hbuf[0][j] = 0.0f;
    float hold = 0.0f;
    __syncthreads();

    float* outb = out + (size_t)b * TT * HH;

    // --- main loop: unroll 16 so all ring indices are static -----------------
    for (int t0 = 0; t0 < TT; t0 += 16) {
        #pragma unroll
        for (int pp = 0; pp < 16; pp++) {
            const int t   = t0 + pp;
            const int cur = t & 1;

            // acc = bias + OMA*h_j + [h ; x_t] . [aW_hh[j,:] | aW_in[j,:]]
            u64 a0 = BIAS2, a1 = 0, a2 = 0, a3 = 0;
            ffma2(a1, pack2(hold, 0.0f), OMA2);

            const ulonglong2* hv = (const ulonglong2*)hbuf[cur];   // 16 LDS.128
            #pragma unroll
            for (int i = 0; i < HH / 4; i++) {
                ulonglong2 hq = hv[i];
                if (i & 1) { ffma2(a2, hq.x, wk[2 * i]); ffma2(a3, hq.y, wk[2 * i + 1]); }
                else       { ffma2(a0, hq.x, wk[2 * i]); ffma2(a1, hq.y, wk[2 * i + 1]); }
            }
            const ulonglong2* xv = (const ulonglong2*)xbuf[t & 15]; // 8 LDS.128
            #pragma unroll
            for (int i = 0; i < DD / 4; i++) {
                ulonglong2 xq = xv[i];
                if (i & 1) { ffma2(a2, xq.x, wi[2 * i]); ffma2(a3, xq.y, wi[2 * i + 1]); }
                else       { ffma2(a0, xq.x, wi[2 * i]); ffma2(a1, xq.y, wi[2 * i + 1]); }
            }
            float2 sf = unpack2(add2(add2(a0, a1), add2(a2, a3)));
            float hnew = fmaxf(sf.x + sf.y, 0.0f);

            hbuf[cur ^ 1][j] = hnew;                 // STS.32 (serial chain)
            outb[(size_t)t * HH + j] = hnew;         // coalesced STG.32
            hold = hnew;

            // Warp 0 (uniform branch): publish x[t+8] from the register ring
            // into smem slot (t+8)&15 (last read at step t-8: barrier-ordered;
            // never equal to this step's read slot t&15). Refill with x[t+16],
            // index clamped so the load is unconditional (clamped values are
            // stored into slots that are never consumed).
            if (stager) {
                xbuf[(t + 8) & 15][l] = xr[pp & 7];
                const int tl = (t + 16 < TT) ? (t + 16) : (TT - 1);
                xr[pp & 7] = xg[(size_t)tl * DD + l];
            }
            __syncthreads();                         // one 2-warp barrier per step
        }
    }

    // h_last appended after outputs
    out[(size_t)BB * TT * HH + (size_t)b * HH + j] = hold;
}

extern "C" void kernel_launch(void* const* d_in, const int* in_sizes, int n_in,
                              void* d_out, int out_size) {
    (void)in_sizes; (void)n_in; (void)out_size;
    const float* x    = (const float*)d_in[0];
    // d_in[1] = seq_lengths: forward no-op (mask only gates gradients)
    const float* W_in = (const float*)d_in[2];
    const float* b_in = (const float*)d_in[3];
    const float* W_hh = (const float*)d_in[4];
    const float* b_hh = (const float*)d_in[5];

    ctrnn_aug_kernel<<<BB, HH>>>(x, W_in, b_in, W_hh, b_hh, (float*)d_out);
}